// round 1
// baseline (speedup 1.0000x reference)
#include <cuda_runtime.h>
#include <math.h>

#define Bn  128
#define NAn 8
#define ADn 16
#define DMn 512
#define DIn 1024
#define DSn 32
#define DCn 4
#define DRn 32
#define NBn 4
#define ODn 128

// ---------------- scratch state (no allocations allowed) ----------------
__device__ float g_x[Bn*DMn];        // residual stream
__device__ float g_ctx[Bn*DMn];      // per-step context
__device__ float g_xc[Bn*DIn];       // silu(conv) output
__device__ float g_sz[Bn*DIn];       // silu(z)
__device__ float g_ys[Bn*DIn];       // y * silu(z)
__device__ float g_aprev[Bn*ADn];    // previous action
__device__ float g_part[2][Bn*DMn];  // split-K partials for out GEMM
__device__ float g_hist[8*4*Bn*DIn]; // conv history ring [inst][slot][b*DI+d]
__device__ float g_negeA[8*DIn*DSn]; // -exp(A_log), layout [inst][s*DI+d]
__device__ float g_h[8*DSn*Bn*DIn];  // SSM state [inst][s][b*DI+d]  (134MB)

__device__ __forceinline__ float sigmoidf_(float x){ return 1.f/(1.f+__expf(-x)); }
__device__ __forceinline__ float siluf_(float x){ return x*sigmoidf_(x); }
__device__ __forceinline__ float softplusf_(float x){ return (x>20.f)? x : log1pf(__expf(x)); }

// ---------------- precompute -exp(A_log), transposed to [s][d] ----------------
__global__ void kPrep(const float* __restrict__ Als, const float* __restrict__ Alc){
  int idx = blockIdx.x*blockDim.x + threadIdx.x;
  if (idx >= 8*DIn*DSn) return;
  int inst = idx >> 15;               // / (DIn*DSn)
  int e    = idx & (DIn*DSn - 1);
  int d = e >> 5, s = e & 31;
  int v = inst & 1, nb = inst >> 1;
  const float* src = (v ? Alc : Als) + nb*DIn*DSn;
  g_negeA[inst*DIn*DSn + s*DIn + d] = -__expf(src[d*DSn + s]);
}

// ---------------- per NA-step: x = a_prev@W_embed + b_embed ; ctx ----------------
__global__ void kEmbed(const float* __restrict__ obs_rep, const float* __restrict__ obs,
                       const float* __restrict__ We, const float* __restrict__ be,
                       const float* __restrict__ Wo, int i){
  __shared__ float sobs[8][ODn];
  __shared__ float sap[8][ADn];
  int t = threadIdx.x;
  int c0 = blockIdx.x*128, b0 = blockIdx.y*8;
  for (int e=t; e<8*ODn; e+=256){ int r=e>>7, o=e&127; sobs[r][o] = obs[((b0+r)*NAn+i)*ODn + o]; }
  if (i>0) for (int e=t; e<8*ADn; e+=256){ int r=e>>4, a=e&15; sap[r][a]=g_aprev[(b0+r)*ADn+a]; }
  __syncthreads();
  for (int e=t; e<8*128; e+=256){
    int r=e>>7, c=c0+(e&127), b=b0+r;
    float xv = be[c];
    if (i>0){
      #pragma unroll
      for (int a=0;a<ADn;a++) xv += sap[r][a]*We[a*DMn+c];
    }
    float cv = obs_rep[(b*NAn+i)*DMn + c];
    #pragma unroll 8
    for (int o=0;o<ODn;o++) cv += sobs[r][o]*Wo[o*DMn+c];
    g_x[b*DMn+c]=xv;
    g_ctx[b*DMn+c]=cv;
  }
}

// ---------------- kA: fused LN(+ctx) -> GEMM1 -> conv/silu epilogue ----------------
// grid(64, 2): 32-wide N tiles over 2048, 64-row M tiles over 128. 256 threads.
__global__ void kA(const float* __restrict__ Win, const float* __restrict__ lnw,
                   const float* __restrict__ cw, const float* __restrict__ cb,
                   int useCtx, int inst, int step){
  __shared__ float As[32][66];
  __shared__ float Bs[32][32];
  __shared__ float smu[64], srs[64];
  int t = threadIdx.x;
  int n0 = blockIdx.x*32, m0 = blockIdx.y*64;
  int w = t>>5, lane = t&31;
  // LayerNorm stats for this block's 64 rows
  for (int r=w; r<64; r+=8){
    const float* xr = g_x + (m0+r)*DMn;
    float s=0.f, q=0.f;
    for (int k=lane;k<DMn;k+=32){ float v=xr[k]; s+=v; q+=v*v; }
    for (int o=16;o;o>>=1){ s+=__shfl_xor_sync(0xffffffffu,s,o); q+=__shfl_xor_sync(0xffffffffu,q,o); }
    if (lane==0){ float m=s*(1.f/DMn); smu[r]=m; srs[r]=rsqrtf(q*(1.f/DMn)-m*m+1e-5f); }
  }
  __syncthreads();
  int ty=t>>3, tx=t&7;  // ty: 32 row-pairs, tx: 8 col-quads
  float acc[2][4] = {{0,0,0,0},{0,0,0,0}};
  for (int kc=0; kc<DMn; kc+=32){
    for (int e=t; e<64*32; e+=256){
      int m=e>>5, k=e&31;
      float v = g_x[(m0+m)*DMn + kc+k];
      v = (v - smu[m])*srs[m]*lnw[kc+k];
      if (useCtx) v += g_ctx[(m0+m)*DMn + kc+k];
      As[k][m] = v;
    }
    for (int e=t; e<32*32; e+=256){
      int k=e>>5, n=e&31;
      Bs[k][n] = Win[(kc+k)*(2*DIn) + n0+n];
    }
    __syncthreads();
    #pragma unroll
    for (int k=0;k<32;k++){
      float a0=As[k][ty*2], a1=As[k][ty*2+1];
      float4 bq = *(const float4*)&Bs[k][tx*4];
      acc[0][0]+=a0*bq.x; acc[0][1]+=a0*bq.y; acc[0][2]+=a0*bq.z; acc[0][3]+=a0*bq.w;
      acc[1][0]+=a1*bq.x; acc[1][1]+=a1*bq.y; acc[1][2]+=a1*bq.z; acc[1][3]+=a1*bq.w;
    }
    __syncthreads();
  }
  int slot = step & 3;
  #pragma unroll
  for (int r=0;r<2;r++){
    int m = m0 + ty*2 + r;
    #pragma unroll
    for (int c=0;c<4;c++){
      int n = n0 + tx*4 + c;
      float v = acc[r][c];
      if (n < DIn){
        int d = n;
        g_hist[((inst*4+slot)*Bn + m)*DIn + d] = v;
        float conv = cb[d] + cw[3*DIn+d]*v;
        if (step>=1) conv += cw[2*DIn+d]*g_hist[((inst*4+((step-1)&3))*Bn + m)*DIn + d];
        if (step>=2) conv += cw[1*DIn+d]*g_hist[((inst*4+((step-2)&3))*Bn + m)*DIn + d];
        if (step>=3) conv += cw[0*DIn+d]*g_hist[((inst*4+((step-3)&3))*Bn + m)*DIn + d];
        g_xc[m*DIn+d] = siluf_(conv);
      } else {
        int d = n - DIn;
        g_sz[m*DIn+d] = siluf_(v);
      }
    }
  }
}

// ---------------- kBC: fused dbc -> delta -> SSM state -> y*silu(z) (1 block/row) ----------------
__global__ void kBC(const float* __restrict__ Wx, const float* __restrict__ Wdt,
                    const float* __restrict__ dtb, const float* __restrict__ Dp,
                    int inst, int step){
  __shared__ float sxc[DIn];
  __shared__ float spart[2][96];
  __shared__ float sdbc[96];
  int b = blockIdx.x, t = threadIdx.x;
  for (int d=t; d<DIn; d+=256) sxc[d]=g_xc[b*DIn+d];
  __syncthreads();
  if (t < 192){
    int j=t%96, p=t/96;
    const float* base = Wx + j;
    const float* xb = sxc + p*512;
    int off = p*512;
    float s0=0,s1=0,s2=0,s3=0;
    for (int d=0; d<512; d+=4){
      s0 += xb[d+0]*base[(off+d+0)*96];
      s1 += xb[d+1]*base[(off+d+1)*96];
      s2 += xb[d+2]*base[(off+d+2)*96];
      s3 += xb[d+3]*base[(off+d+3)*96];
    }
    spart[p][j] = (s0+s1)+(s2+s3);
  }
  __syncthreads();
  if (t < 96) sdbc[t] = spart[0][t] + spart[1][t];
  __syncthreads();
  const float* Bm = sdbc + DRn;
  const float* Cm = sdbc + DRn + DSn;
  #pragma unroll
  for (int q=0;q<4;q++){
    int d = t + q*256;
    float acc = dtb[d];
    #pragma unroll
    for (int r=0;r<DRn;r++) acc += sdbc[r]*Wdt[r*DIn+d];
    float delta = softplusf_(acc);
    float xc = sxc[d];
    float dxc = delta*xc;
    const float* nA = g_negeA + inst*DIn*DSn;
    float* hb = g_h + (size_t)(inst*DSn)*(Bn*DIn) + b*DIn + d;
    float y = 0.f;
    #pragma unroll
    for (int s=0;s<DSn;s++){
      float dA = __expf(delta * nA[s*DIn + d]);
      float hv = (step>0) ? hb[(size_t)s*(Bn*DIn)] : 0.f;
      hv = dA*hv + dxc*Bm[s];
      hb[(size_t)s*(Bn*DIn)] = hv;
      y += hv*Cm[s];
    }
    y += Dp[d]*xc;
    g_ys[b*DIn+d] = y*g_sz[b*DIn+d];
  }
}

// ---------------- kD: out GEMM [128,1024]x[1024,512], split-K=2 into partials ----------------
__global__ void kD(const float* __restrict__ Wout){
  __shared__ float As[32][33];
  __shared__ float Bs[32][32];
  int t=threadIdx.x;
  int n0=blockIdx.x*32, m0=blockIdx.y*32, kz=blockIdx.z;
  int ty=t>>4, tx=t&15;
  float a00=0,a01=0,a10=0,a11=0;
  for (int kc=kz*512; kc<kz*512+512; kc+=32){
    for (int e=t;e<32*32;e+=256){ int m=e>>5,k=e&31; As[k][m]=g_ys[(m0+m)*DIn + kc+k]; }
    for (int e=t;e<32*32;e+=256){ int k=e>>5,n=e&31; Bs[k][n]=Wout[(kc+k)*DMn + n0+n]; }
    __syncthreads();
    #pragma unroll
    for (int k=0;k<32;k++){
      float x0=As[k][ty*2], x1=As[k][ty*2+1];
      float y0=Bs[k][tx*2], y1=Bs[k][tx*2+1];
      a00+=x0*y0; a01+=x0*y1; a10+=x1*y0; a11+=x1*y1;
    }
    __syncthreads();
  }
  float* P = g_part[kz];
  int m=m0+ty*2, n=n0+tx*2;
  P[m*DMn+n]=a00; P[m*DMn+n+1]=a01; P[(m+1)*DMn+n]=a10; P[(m+1)*DMn+n+1]=a11;
}

// ---------------- kAdd: x += partial0 + partial1 ----------------
__global__ void kAdd(){
  int e = blockIdx.x*256 + threadIdx.x;
  float4* xp = reinterpret_cast<float4*>(g_x);
  const float4* p0 = reinterpret_cast<const float4*>(g_part[0]);
  const float4* p1 = reinterpret_cast<const float4*>(g_part[1]);
  float4 a=xp[e], u=p0[e], v=p1[e];
  a.x+=u.x+v.x; a.y+=u.y+v.y; a.z+=u.z+v.z; a.w+=u.w+v.w;
  xp[e]=a;
}

// ---------------- kHead: LN -> head GEMM -> raw/act/logprob, writes outputs ----------------
__global__ void kHead(const float* __restrict__ lno, const float* __restrict__ Wh,
                      const float* __restrict__ lstd, const float* __restrict__ eps,
                      float* __restrict__ out, int i){
  __shared__ float r1[128], r2[128];
  __shared__ float spart[128];
  __shared__ float mu_s, rs_s;
  int b = blockIdx.x, t = threadIdx.x;
  const float* xr = g_x + b*DMn;
  float s=0,q=0;
  for (int k=t;k<DMn;k+=128){ float v=xr[k]; s+=v; q+=v*v; }
  r1[t]=s; r2[t]=q; __syncthreads();
  for (int o=64;o>=1;o>>=1){ if (t<o){ r1[t]+=r1[t+o]; r2[t]+=r2[t+o]; } __syncthreads(); }
  if (t==0){ float m=r1[0]*(1.f/DMn); mu_s=m; rs_s = rsqrtf(r2[0]*(1.f/DMn)-m*m+1e-5f); }
  __syncthreads();
  int j = t&15, seg = t>>4;
  float p=0.f;
  for (int k=seg*64; k<seg*64+64; k++){
    float u = (xr[k]-mu_s)*rs_s*lno[k];
    p += u*Wh[k*ADn + j];
  }
  spart[t]=p; __syncthreads();
  if (t < 16){
    float m = 0;
    #pragma unroll
    for (int sg=0;sg<8;sg++) m += spart[sg*16 + t];
    float std = softplusf_(lstd[t]);
    float e = eps[(b*NAn+i)*ADn + t];
    float raw = m + std*e;
    float act = tanhf(raw);
    int oidx = (b*NAn+i)*ADn + t;
    out[oidx] = act;                 // acts  [0, 16384)
    out[17408 + oidx] = raw;         // raws  [17408, 33792)
    g_aprev[b*ADn+t] = act;
    float term = -0.5f*e*e - logf(std)
               - 2.f*(0.69314718055994531f - raw - softplusf_(-2.f*raw));
    for (int o=8;o;o>>=1) term += __shfl_xor_sync(0xffffu, term, o);
    if (t==0) out[16384 + b*NAn + i] = term - 0.5f*ADn*1.8378770664093453f; // logs [16384,17408)
  }
}

extern "C" void kernel_launch(void* const* d_in, const int* in_sizes, int n_in,
                              void* d_out, int out_size){
  (void)in_sizes; (void)n_in; (void)out_size;
  const float* obs_rep =(const float*)d_in[0];
  const float* obs     =(const float*)d_in[1];
  const float* eps     =(const float*)d_in[2];
  const float* W_embed =(const float*)d_in[3];
  const float* b_embed =(const float*)d_in[4];
  const float* W_obs   =(const float*)d_in[5];
  const float* ln1     =(const float*)d_in[6];
  const float* ln2     =(const float*)d_in[7];
  const float* ln_out  =(const float*)d_in[8];
  const float* W_head  =(const float*)d_in[9];
  const float* log_std =(const float*)d_in[10];
  const float* ip [2]={(const float*)d_in[11],(const float*)d_in[20]};
  const float* cwp[2]={(const float*)d_in[12],(const float*)d_in[21]};
  const float* cbp[2]={(const float*)d_in[13],(const float*)d_in[22]};
  const float* xpj[2]={(const float*)d_in[14],(const float*)d_in[23]};
  const float* dtp[2]={(const float*)d_in[15],(const float*)d_in[24]};
  const float* dtb[2]={(const float*)d_in[16],(const float*)d_in[25]};
  const float* alp[2]={(const float*)d_in[17],(const float*)d_in[26]};
  const float* Dpp[2]={(const float*)d_in[18],(const float*)d_in[27]};
  const float* opp[2]={(const float*)d_in[19],(const float*)d_in[28]};
  const float* lnp[2]={ln1, ln2};
  float* out=(float*)d_out;

  kPrep<<<(8*DIn*DSn+255)/256,256>>>(alp[0], alp[1]);
  for (int i=0;i<NAn;i++){
    kEmbed<<<dim3(4,16),256>>>(obs_rep, obs, W_embed, b_embed, W_obs, i);
    for (int nb=0;nb<NBn;nb++){
      for (int v=0;v<2;v++){
        int inst = nb*2+v;
        kA<<<dim3(64,2),256>>>(ip[v] + (size_t)nb*DMn*2*DIn,
                               lnp[v] + nb*DMn,
                               cwp[v] + nb*DCn*DIn,
                               cbp[v] + nb*DIn,
                               v, inst, i);
        kBC<<<Bn,256>>>(xpj[v] + nb*DIn*96,
                        dtp[v] + nb*DRn*DIn,
                        dtb[v] + nb*DIn,
                        Dpp[v] + nb*DIn,
                        inst, i);
        kD<<<dim3(16,4,2),256>>>(opp[v] + (size_t)nb*DIn*DMn);
        kAdd<<<64,256>>>();
      }
    }
    kHead<<<Bn,128>>>(ln_out, W_head, log_std, eps, out, i);
  }
}

// round 3
// speedup vs baseline: 2.5205x; 2.5205x over previous
#include <cuda_runtime.h>
#include <math.h>

#define Bn  128
#define NAn 8
#define ADn 16
#define DMn 512
#define DIn 1024
#define DSn 32
#define DCn 4
#define DRn 32
#define NBn 4
#define ODn 128

// ---------------- scratch state (no allocations allowed) ----------------
__device__ float g_x[Bn*DMn];          // residual stream
__device__ float g_ctx[Bn*DMn];        // per-step context
__device__ float g_xn[Bn*DMn];         // LN'd (+ctx) input for next consumer
__device__ float g_xc[Bn*DIn];         // silu(conv) output
__device__ float g_sz[Bn*DIn];         // silu(z)
__device__ float g_ys[Bn*DIn];         // y * silu(z)
__device__ float g_aprev[Bn*ADn];      // previous action
__device__ float g_part[4][Bn*DMn];    // split-K partials for out GEMM
__device__ float g_hist[8*4*Bn*DIn];   // conv history ring [inst][slot][b*DI+d]
__device__ float g_negeA[8*DIn*DSn];   // -exp(A_log), layout [inst][s*DI+d]
__device__ float g_h[8*DSn*Bn*DIn];    // SSM state [inst][s][b*DI+d]

__device__ __forceinline__ float sigmoidf_(float x){ return 1.f/(1.f+__expf(-x)); }
__device__ __forceinline__ float siluf_(float x){ return x*sigmoidf_(x); }
__device__ __forceinline__ float softplusf_(float x){ return (x>20.f)? x : log1pf(__expf(x)); }

// ---------------- precompute -exp(A_log), transposed to [s][d] ----------------
__global__ void kPrep(const float* __restrict__ Als, const float* __restrict__ Alc){
  int idx = blockIdx.x*blockDim.x + threadIdx.x;
  if (idx >= 8*DIn*DSn) return;
  int inst = idx >> 15;
  int e    = idx & (DIn*DSn - 1);
  int d = e >> 5, s = e & 31;
  int v = inst & 1, nb = inst >> 1;
  const float* src = (v ? Alc : Als) + nb*DIn*DSn;
  g_negeA[inst*DIn*DSn + s*DIn + d] = -__expf(src[d*DSn + s]);
}

// ---------------- kEmbed: x = a_prev@We + be ; ctx ; LN(x)*ln1[0] -> g_xn ----------------
// grid 128 (one block per batch row), 256 threads
__global__ void __launch_bounds__(256) kEmbed(
    const float* __restrict__ obs_rep, const float* __restrict__ obs,
    const float* __restrict__ We, const float* __restrict__ be,
    const float* __restrict__ Wo, const float* __restrict__ ln0, int i){
  __shared__ float sobs[ODn];
  __shared__ float sap[ADn];
  __shared__ float rs_[8], rq_[8];
  __shared__ float smu, srs;
  int b = blockIdx.x, t = threadIdx.x;
  if (t < ODn) sobs[t] = obs[(b*NAn+i)*ODn + t];
  if (i > 0 && t < ADn) sap[t] = g_aprev[b*ADn + t];
  __syncthreads();
  float xv[2];
  #pragma unroll
  for (int u=0; u<2; u++){
    int c = t + 256*u;
    float x = be[c];
    if (i > 0){
      #pragma unroll
      for (int a=0; a<ADn; a++) x += sap[a]*We[a*DMn + c];
    }
    float cv = obs_rep[(b*NAn+i)*DMn + c];
    #pragma unroll 4
    for (int o=0; o<ODn; o++) cv += sobs[o]*Wo[o*DMn + c];
    g_x[b*DMn + c] = x;
    g_ctx[b*DMn + c] = cv;
    xv[u] = x;
  }
  float s = xv[0]+xv[1], q = xv[0]*xv[0]+xv[1]*xv[1];
  for (int o=16;o;o>>=1){ s+=__shfl_xor_sync(0xffffffffu,s,o); q+=__shfl_xor_sync(0xffffffffu,q,o); }
  if ((t&31)==0){ rs_[t>>5]=s; rq_[t>>5]=q; }
  __syncthreads();
  if (t==0){
    float S=0,Q=0;
    #pragma unroll
    for (int w=0;w<8;w++){ S+=rs_[w]; Q+=rq_[w]; }
    float m=S*(1.f/DMn); smu=m; srs=rsqrtf(Q*(1.f/DMn)-m*m+1e-5f);
  }
  __syncthreads();
  float m=smu, r=srs;
  #pragma unroll
  for (int u=0; u<2; u++){
    int c = t + 256*u;
    g_xn[b*DMn + c] = (xv[u]-m)*r*ln0[c];
  }
}

// ---------------- kA: pure GEMM g_xn[128,512]@Win[512,2048] + conv/silu epilogue ----------------
// grid(64 n-tiles, 4 m-tiles) = 256 blocks, 256 threads, 32x32 tile, 2x2 per thread
__global__ void __launch_bounds__(256) kA(const float* __restrict__ Win,
                   const float* __restrict__ cw, const float* __restrict__ cb,
                   int inst, int step){
  __shared__ float As[32][33];
  __shared__ float Bs[32][32];
  int t = threadIdx.x;
  int n0 = blockIdx.x*32, m0 = blockIdx.y*32;
  int ty = t>>4, tx = t&15;
  int lm = t>>3, lk = (t&7)*4;
  float acc[2][2] = {{0.f,0.f},{0.f,0.f}};
  for (int kc=0; kc<DMn; kc+=32){
    float4 av = *(const float4*)&g_xn[(m0+lm)*DMn + kc + lk];
    As[lk  ][lm]=av.x; As[lk+1][lm]=av.y; As[lk+2][lm]=av.z; As[lk+3][lm]=av.w;
    *(float4*)&Bs[lm][lk] = *(const float4*)&Win[(kc+lm)*(2*DIn) + n0 + lk];
    __syncthreads();
    #pragma unroll
    for (int k=0;k<32;k++){
      float a0=As[k][ty*2], a1=As[k][ty*2+1];
      float b0=Bs[k][tx*2], b1=Bs[k][tx*2+1];
      acc[0][0]+=a0*b0; acc[0][1]+=a0*b1;
      acc[1][0]+=a1*b0; acc[1][1]+=a1*b1;
    }
    __syncthreads();
  }
  int slot = step & 3;
  #pragma unroll
  for (int r=0;r<2;r++){
    int m = m0 + ty*2 + r;
    #pragma unroll
    for (int c=0;c<2;c++){
      int n = n0 + tx*2 + c;
      float v = acc[r][c];
      if (n < DIn){
        int d = n;
        g_hist[((inst*4+slot)*Bn + m)*DIn + d] = v;
        float conv = cb[d] + cw[3*DIn+d]*v;
        if (step>=1) conv += cw[2*DIn+d]*g_hist[((inst*4+((step-1)&3))*Bn + m)*DIn + d];
        if (step>=2) conv += cw[1*DIn+d]*g_hist[((inst*4+((step-2)&3))*Bn + m)*DIn + d];
        if (step>=3) conv += cw[0*DIn+d]*g_hist[((inst*4+((step-3)&3))*Bn + m)*DIn + d];
        g_xc[m*DIn+d] = siluf_(conv);
      } else {
        int d = n - DIn;
        g_sz[m*DIn+d] = siluf_(v);
      }
    }
  }
}

// ---------------- kB: dbc (coalesced) -> delta -> SSM -> y*silu(z) ----------------
// grid 128 (per b), 512 threads
__global__ void __launch_bounds__(512) kB(const float* __restrict__ Wx,
                   const float* __restrict__ Wdt, const float* __restrict__ dtb,
                   const float* __restrict__ Dp, int inst, int step){
  __shared__ float sxc[DIn];
  __shared__ float spart[4][96];
  __shared__ float sdbc[96];
  int b = blockIdx.x, t = threadIdx.x;
  ((float2*)sxc)[t] = ((const float2*)(g_xc + b*DIn))[t];
  __syncthreads();
  if (t < 384){
    int p = t/96, j = t - p*96;
    const float* xb = sxc + p*256;
    const float* wb = Wx + (size_t)p*256*96 + j;
    float a0=0.f,a1=0.f,a2=0.f,a3=0.f;
    #pragma unroll 8
    for (int d=0; d<256; d+=4){
      a0 += xb[d+0]*wb[(d+0)*96];
      a1 += xb[d+1]*wb[(d+1)*96];
      a2 += xb[d+2]*wb[(d+2)*96];
      a3 += xb[d+3]*wb[(d+3)*96];
    }
    spart[p][j] = (a0+a1)+(a2+a3);
  }
  __syncthreads();
  if (t < 96) sdbc[t] = (spart[0][t]+spart[1][t])+(spart[2][t]+spart[3][t]);
  __syncthreads();
  const float* Bm = sdbc + DRn;
  const float* Cm = sdbc + DRn + DSn;
  #pragma unroll
  for (int q=0;q<2;q++){
    int d = t + q*512;
    float acc = dtb[d];
    #pragma unroll
    for (int r=0;r<DRn;r++) acc += sdbc[r]*Wdt[r*DIn+d];
    float delta = softplusf_(acc);
    float xc = sxc[d];
    float dxc = delta*xc;
    const float* nA = g_negeA + inst*DIn*DSn + d;
    float* hb = g_h + (size_t)(inst*DSn)*(Bn*DIn) + b*DIn + d;
    float y = 0.f;
    #pragma unroll
    for (int s=0;s<DSn;s++){
      float dA = __expf(delta * nA[(size_t)s*DIn]);
      float hv = (step>0) ? hb[(size_t)s*(Bn*DIn)] : 0.f;
      hv = dA*hv + dxc*Bm[s];
      hb[(size_t)s*(Bn*DIn)] = hv;
      y += hv*Cm[s];
    }
    y += Dp[d]*xc;
    g_ys[b*DIn+d] = y*g_sz[b*DIn+d];
  }
}

// ---------------- kD: out GEMM split-K=4 into g_part ----------------
// grid(16 n, 4 m, 4 kz), 256 threads, 32x32 tile, 2x2 per thread
__global__ void __launch_bounds__(256) kD(const float* __restrict__ Wout){
  __shared__ float As[32][33];
  __shared__ float Bs[32][32];
  int t = threadIdx.x;
  int n0 = blockIdx.x*32, m0 = blockIdx.y*32, kz = blockIdx.z;
  int ty = t>>4, tx = t&15;
  int lm = t>>3, lk = (t&7)*4;
  float acc[2][2] = {{0.f,0.f},{0.f,0.f}};
  for (int kc=kz*256; kc<kz*256+256; kc+=32){
    float4 av = *(const float4*)&g_ys[(m0+lm)*DIn + kc + lk];
    As[lk  ][lm]=av.x; As[lk+1][lm]=av.y; As[lk+2][lm]=av.z; As[lk+3][lm]=av.w;
    *(float4*)&Bs[lm][lk] = *(const float4*)&Wout[(kc+lm)*DMn + n0 + lk];
    __syncthreads();
    #pragma unroll
    for (int k=0;k<32;k++){
      float a0=As[k][ty*2], a1=As[k][ty*2+1];
      float b0=Bs[k][tx*2], b1=Bs[k][tx*2+1];
      acc[0][0]+=a0*b0; acc[0][1]+=a0*b1;
      acc[1][0]+=a1*b0; acc[1][1]+=a1*b1;
    }
    __syncthreads();
  }
  float* P = g_part[kz];
  int m = m0+ty*2, n = n0+tx*2;
  P[m*DMn+n]=acc[0][0]; P[m*DMn+n+1]=acc[0][1];
  P[(m+1)*DMn+n]=acc[1][0]; P[(m+1)*DMn+n+1]=acc[1][1];
}

// ---------------- kAddLN: x += sum(partials); g_xn = LN(x)*lnw (+ctx) ----------------
// grid 128 (per b), 256 threads (float2 per thread)
__global__ void __launch_bounds__(256) kAddLN(const float* __restrict__ lnw, int useCtx){
  __shared__ float rs_[8], rq_[8];
  __shared__ float smu, srs;
  int b = blockIdx.x, t = threadIdx.x;
  int c = 2*t;
  float2 x = ((const float2*)(g_x + b*DMn))[t];
  #pragma unroll
  for (int p=0;p<4;p++){
    float2 v = ((const float2*)(g_part[p] + b*DMn))[t];
    x.x += v.x; x.y += v.y;
  }
  ((float2*)(g_x + b*DMn))[t] = x;
  float s = x.x+x.y, q = x.x*x.x+x.y*x.y;
  for (int o=16;o;o>>=1){ s+=__shfl_xor_sync(0xffffffffu,s,o); q+=__shfl_xor_sync(0xffffffffu,q,o); }
  if ((t&31)==0){ rs_[t>>5]=s; rq_[t>>5]=q; }
  __syncthreads();
  if (t==0){
    float S=0,Q=0;
    #pragma unroll
    for (int w=0;w<8;w++){ S+=rs_[w]; Q+=rq_[w]; }
    float m=S*(1.f/DMn); smu=m; srs=rsqrtf(Q*(1.f/DMn)-m*m+1e-5f);
  }
  __syncthreads();
  float m=smu, r=srs;
  float2 xn;
  xn.x = (x.x-m)*r*lnw[c];
  xn.y = (x.y-m)*r*lnw[c+1];
  if (useCtx){
    float2 cv = ((const float2*)(g_ctx + b*DMn))[t];
    xn.x += cv.x; xn.y += cv.y;
  }
  ((float2*)(g_xn + b*DMn))[t] = xn;
}

// ---------------- kHead: head GEMM from g_xn -> raw/act/logprob ----------------
__global__ void __launch_bounds__(128) kHead(const float* __restrict__ Wh,
                      const float* __restrict__ lstd, const float* __restrict__ eps,
                      float* __restrict__ out, int i){
  __shared__ float spart[128];
  int b = blockIdx.x, t = threadIdx.x;
  const float* xn = g_xn + b*DMn;
  int j = t&15, seg = t>>4;
  float p = 0.f;
  for (int k=seg*64; k<seg*64+64; k++) p += xn[k]*Wh[k*ADn + j];
  spart[t] = p; __syncthreads();
  if (t < 16){
    float m = 0.f;
    #pragma unroll
    for (int sg=0;sg<8;sg++) m += spart[sg*16 + t];
    float std = softplusf_(lstd[t]);
    float e = eps[(b*NAn+i)*ADn + t];
    float raw = m + std*e;
    float act = tanhf(raw);
    int oidx = (b*NAn+i)*ADn + t;
    out[oidx] = act;
    out[17408 + oidx] = raw;
    g_aprev[b*ADn+t] = act;
    float term = -0.5f*e*e - logf(std)
               - 2.f*(0.69314718055994531f - raw - softplusf_(-2.f*raw));
    for (int o=8;o;o>>=1) term += __shfl_xor_sync(0xffffu, term, o);
    if (t==0) out[16384 + b*NAn + i] = term - 0.5f*ADn*1.8378770664093453f;
  }
}

extern "C" void kernel_launch(void* const* d_in, const int* in_sizes, int n_in,
                              void* d_out, int out_size){
  (void)in_sizes; (void)n_in; (void)out_size;
  const float* obs_rep =(const float*)d_in[0];
  const float* obs     =(const float*)d_in[1];
  const float* eps     =(const float*)d_in[2];
  const float* W_embed =(const float*)d_in[3];
  const float* b_embed =(const float*)d_in[4];
  const float* W_obs   =(const float*)d_in[5];
  const float* ln1     =(const float*)d_in[6];
  const float* ln2     =(const float*)d_in[7];
  const float* ln_out  =(const float*)d_in[8];
  const float* W_head  =(const float*)d_in[9];
  const float* log_std =(const float*)d_in[10];
  const float* ip [2]={(const float*)d_in[11],(const float*)d_in[20]};
  const float* cwp[2]={(const float*)d_in[12],(const float*)d_in[21]};
  const float* cbp[2]={(const float*)d_in[13],(const float*)d_in[22]};
  const float* xpj[2]={(const float*)d_in[14],(const float*)d_in[23]};
  const float* dtp[2]={(const float*)d_in[15],(const float*)d_in[24]};
  const float* dtb[2]={(const float*)d_in[16],(const float*)d_in[25]};
  const float* alp[2]={(const float*)d_in[17],(const float*)d_in[26]};
  const float* Dpp[2]={(const float*)d_in[18],(const float*)d_in[27]};
  const float* opp[2]={(const float*)d_in[19],(const float*)d_in[28]};
  float* out=(float*)d_out;

  kPrep<<<(8*DIn*DSn+255)/256,256>>>(alp[0], alp[1]);
  for (int i=0;i<NAn;i++){
    kEmbed<<<Bn,256>>>(obs_rep, obs, W_embed, b_embed, W_obs, ln1 /*block 0*/, i);
    for (int nb=0;nb<NBn;nb++){
      for (int v=0;v<2;v++){
        int inst = nb*2+v;
        kA<<<dim3(64,4),256>>>(ip[v] + (size_t)nb*DMn*2*DIn,
                               cwp[v] + nb*DCn*DIn,
                               cbp[v] + nb*DIn,
                               inst, i);
        kB<<<Bn,512>>>(xpj[v] + (size_t)nb*DIn*96,
                       dtp[v] + nb*DRn*DIn,
                       dtb[v] + nb*DIn,
                       Dpp[v] + nb*DIn,
                       inst, i);
        kD<<<dim3(16,4,4),256>>>(opp[v] + (size_t)nb*DIn*DMn);
        // next consumer's LN weights
        const float* nlw; int nuc;
        if (v==0){ nlw = ln2 + nb*DMn; nuc = 1; }
        else if (nb < NBn-1){ nlw = ln1 + (nb+1)*DMn; nuc = 0; }
        else { nlw = ln_out; nuc = 0; }
        kAddLN<<<Bn,256>>>(nlw, nuc);
      }
    }
    kHead<<<Bn,128>>>(W_head, log_std, eps, out, i);
  }
}

// round 8
// speedup vs baseline: 3.2054x; 1.2718x over previous
#include <cuda_runtime.h>
#include <math.h>

#define Bn  128
#define NAn 8
#define ADn 16
#define DMn 512
#define DIn 1024
#define DSn 32
#define DCn 4
#define DRn 32
#define NBn 4
#define ODn 128

// ---------------- scratch state (no allocations allowed) ----------------
__device__ float g_x[Bn*DMn];          // residual stream
__device__ float g_ctx[Bn*DMn];        // per-step context
__device__ float g_xn[Bn*DMn];         // LN'd (+ctx) input for next consumer
__device__ float g_xc[Bn*DIn];         // silu(conv) output
__device__ float g_sz[Bn*DIn];         // silu(z)
__device__ float g_ys[Bn*DIn];         // y * silu(z)
__device__ float g_aprev[Bn*ADn];      // previous action
__device__ float g_part[4][Bn*DMn];    // split-K partials for out GEMM
__device__ float g_dbcp[8][Bn*96];     // split-K partials for dbc GEMM
__device__ float g_hist[8*4*Bn*DIn];   // conv history ring [inst][slot][b*DI+d]
__device__ float g_negeA[8*DIn*DSn];   // -exp(A_log), layout [inst][s*DI+d]
__device__ float g_h[8*DSn*Bn*DIn];    // SSM state [inst][s][b*DI+d]

__device__ __forceinline__ float sigmoidf_(float x){ return 1.f/(1.f+__expf(-x)); }
__device__ __forceinline__ float siluf_(float x){ return x*sigmoidf_(x); }
__device__ __forceinline__ float softplusf_(float x){ return (x>20.f)? x : log1pf(__expf(x)); }

// ---------------- precompute -exp(A_log), transposed to [s][d] ----------------
__global__ void kPrep(const float* __restrict__ Als, const float* __restrict__ Alc){
  int idx = blockIdx.x*blockDim.x + threadIdx.x;
  if (idx >= 8*DIn*DSn) return;
  int inst = idx >> 15;
  int e    = idx & (DIn*DSn - 1);
  int d = e >> 5, s = e & 31;
  int v = inst & 1, nb = inst >> 1;
  const float* src = (v ? Alc : Als) + nb*DIn*DSn;
  g_negeA[inst*DIn*DSn + s*DIn + d] = -__expf(src[d*DSn + s]);
}

// ---------------- kEmbed: x = a_prev@We + be ; ctx ; LN(x)*ln1[0] -> g_xn ----------------
__global__ void __launch_bounds__(256) kEmbed(
    const float* __restrict__ obs_rep, const float* __restrict__ obs,
    const float* __restrict__ We, const float* __restrict__ be,
    const float* __restrict__ Wo, const float* __restrict__ ln0, int i){
  __shared__ float sobs[ODn];
  __shared__ float sap[ADn];
  __shared__ float rs_[8], rq_[8];
  __shared__ float smu, srs;
  int b = blockIdx.x, t = threadIdx.x;
  if (t < ODn) sobs[t] = obs[(b*NAn+i)*ODn + t];
  if (i > 0 && t < ADn) sap[t] = g_aprev[b*ADn + t];
  __syncthreads();
  float xv[2];
  #pragma unroll
  for (int u=0; u<2; u++){
    int c = t + 256*u;
    float x = be[c];
    if (i > 0){
      #pragma unroll
      for (int a=0; a<ADn; a++) x += sap[a]*We[a*DMn + c];
    }
    float cv = obs_rep[(b*NAn+i)*DMn + c];
    #pragma unroll 4
    for (int o=0; o<ODn; o++) cv += sobs[o]*Wo[o*DMn + c];
    g_x[b*DMn + c] = x;
    g_ctx[b*DMn + c] = cv;
    xv[u] = x;
  }
  float s = xv[0]+xv[1], q = xv[0]*xv[0]+xv[1]*xv[1];
  for (int o=16;o;o>>=1){ s+=__shfl_xor_sync(0xffffffffu,s,o); q+=__shfl_xor_sync(0xffffffffu,q,o); }
  if ((t&31)==0){ rs_[t>>5]=s; rq_[t>>5]=q; }
  __syncthreads();
  if (t==0){
    float S=0,Q=0;
    #pragma unroll
    for (int w=0;w<8;w++){ S+=rs_[w]; Q+=rq_[w]; }
    float m=S*(1.f/DMn); smu=m; srs=rsqrtf(Q*(1.f/DMn)-m*m+1e-5f);
  }
  __syncthreads();
  float m=smu, r=srs;
  #pragma unroll
  for (int u=0; u<2; u++){
    int c = t + 256*u;
    g_xn[b*DMn + c] = (xv[u]-m)*r*ln0[c];
  }
}

// ---------------- kA: GEMM g_xn[128,512]@Win[512,2048] + conv/silu epilogue ----------------
__global__ void __launch_bounds__(256) kA(const float* __restrict__ Win,
                   const float* __restrict__ cw, const float* __restrict__ cb,
                   int inst, int step){
  __shared__ float As[32][33];
  __shared__ float Bs[32][32];
  int t = threadIdx.x;
  int n0 = blockIdx.x*32, m0 = blockIdx.y*32;
  int ty = t>>4, tx = t&15;
  int lm = t>>3, lk = (t&7)*4;
  float acc[2][2] = {{0.f,0.f},{0.f,0.f}};
  for (int kc=0; kc<DMn; kc+=32){
    float4 av = *(const float4*)&g_xn[(m0+lm)*DMn + kc + lk];
    As[lk  ][lm]=av.x; As[lk+1][lm]=av.y; As[lk+2][lm]=av.z; As[lk+3][lm]=av.w;
    *(float4*)&Bs[lm][lk] = *(const float4*)&Win[(kc+lm)*(2*DIn) + n0 + lk];
    __syncthreads();
    #pragma unroll
    for (int k=0;k<32;k++){
      float a0=As[k][ty*2], a1=As[k][ty*2+1];
      float b0=Bs[k][tx*2], b1=Bs[k][tx*2+1];
      acc[0][0]+=a0*b0; acc[0][1]+=a0*b1;
      acc[1][0]+=a1*b0; acc[1][1]+=a1*b1;
    }
    __syncthreads();
  }
  int slot = step & 3;
  #pragma unroll
  for (int r=0;r<2;r++){
    int m = m0 + ty*2 + r;
    #pragma unroll
    for (int c=0;c<2;c++){
      int n = n0 + tx*2 + c;
      float v = acc[r][c];
      if (n < DIn){
        int d = n;
        g_hist[((inst*4+slot)*Bn + m)*DIn + d] = v;
        float conv = cb[d] + cw[3*DIn+d]*v;
        if (step>=1) conv += cw[2*DIn+d]*g_hist[((inst*4+((step-1)&3))*Bn + m)*DIn + d];
        if (step>=2) conv += cw[1*DIn+d]*g_hist[((inst*4+((step-2)&3))*Bn + m)*DIn + d];
        if (step>=3) conv += cw[0*DIn+d]*g_hist[((inst*4+((step-3)&3))*Bn + m)*DIn + d];
        g_xc[m*DIn+d] = siluf_(conv);
      } else {
        int d = n - DIn;
        g_sz[m*DIn+d] = siluf_(v);
      }
    }
  }
}

// ---------------- kB1: dbc partial GEMM xc[128,1024]@Wx[1024,96], split-K=8 ----------------
// grid(4 m-tiles, 8 kz), 256 threads. Tile 32m x 96n, K=128 per kz.
__global__ void __launch_bounds__(256) kB1(const float* __restrict__ Wx){
  __shared__ float As[32][33];
  __shared__ float Bs[32][96];
  int t = threadIdx.x;
  int m0 = blockIdx.x*32, k0 = blockIdx.y*128;
  int ty = t>>4, tx = t&15;          // ty: 16 row-pairs, tx: 16 col-groups of 6
  int lm = t>>3, lk = (t&7)*4;
  float acc[2][6];
  #pragma unroll
  for (int r=0;r<2;r++)
    #pragma unroll
    for (int j=0;j<6;j++) acc[r][j]=0.f;
  for (int kc=0; kc<128; kc+=32){
    float4 av = *(const float4*)&g_xc[(m0+lm)*DIn + k0 + kc + lk];
    As[lk  ][lm]=av.x; As[lk+1][lm]=av.y; As[lk+2][lm]=av.z; As[lk+3][lm]=av.w;
    #pragma unroll
    for (int u=0; u<3; u++){
      int e = t + 256*u;             // 768 float4 = 32 rows x 24 float4
      int row = e/24, c4 = e - row*24;
      *(float4*)&Bs[row][c4*4] = *(const float4*)&Wx[(k0+kc+row)*96 + c4*4];
    }
    __syncthreads();
    #pragma unroll
    for (int k=0;k<32;k++){
      float a0=As[k][ty*2], a1=As[k][ty*2+1];
      #pragma unroll
      for (int j=0;j<6;j++){
        float bv = Bs[k][tx*6+j];
        acc[0][j] += a0*bv;
        acc[1][j] += a1*bv;
      }
    }
    __syncthreads();
  }
  float* P = g_dbcp[blockIdx.y];
  #pragma unroll
  for (int r=0;r<2;r++){
    int m = m0 + ty*2 + r;
    #pragma unroll
    for (int j=0;j<6;j++) P[m*96 + tx*6 + j] = acc[r][j];
  }
}

// ---------------- kB2: reduce dbc -> delta -> SSM -> y*silu(z) ----------------
// grid(32 d-groups, 4 b-groups) = 128 blocks x 1024 threads; one thread per (b,d)
__global__ void __launch_bounds__(1024) kB2(const float* __restrict__ Wdt,
                   const float* __restrict__ dtb, const float* __restrict__ Dp,
                   int inst, int step){
  __shared__ float sdbc[32][96];
  __shared__ float sWdt[32][32];
  __shared__ float snA[32][32];
  int t = threadIdx.x;
  int lane = t & 31, brow = t >> 5;
  int d0 = blockIdx.x*32, b0 = blockIdx.y*32;
  int d = d0 + lane, b = b0 + brow;
  { int r = t >> 5, c = t & 31;
    sWdt[r][c] = Wdt[r*DIn + d0 + c];
    snA[r][c]  = g_negeA[inst*DIn*DSn + r*DIn + d0 + c]; }
  #pragma unroll
  for (int u=0; u<3; u++){
    int e = t + 1024*u;              // 3072 = 32 rows x 96 cols
    int rr = e/96, cc = e - rr*96;
    float s = 0.f;
    #pragma unroll
    for (int p=0;p<8;p++) s += g_dbcp[p][(b0+rr)*96 + cc];
    sdbc[rr][cc] = s;
  }
  __syncthreads();
  float acc = dtb[d];
  #pragma unroll
  for (int r=0;r<DRn;r++) acc += sdbc[brow][r]*sWdt[r][lane];
  float delta = softplusf_(acc);
  float xc = g_xc[b*DIn + d];
  float dxc = delta*xc;
  float* hb = g_h + ((size_t)inst*DSn)*(Bn*DIn) + (size_t)b*DIn + d;
  float y = 0.f;
  #pragma unroll
  for (int s=0;s<DSn;s++){
    float dA = __expf(delta * snA[s][lane]);
    float hv = (step>0) ? hb[(size_t)s*(Bn*DIn)] : 0.f;
    hv = dA*hv + dxc*sdbc[brow][32+s];
    hb[(size_t)s*(Bn*DIn)] = hv;
    y += hv*sdbc[brow][64+s];
  }
  y += Dp[d]*xc;
  g_ys[b*DIn + d] = y*g_sz[b*DIn + d];
}

// ---------------- kD: out GEMM split-K=4 into g_part ----------------
__global__ void __launch_bounds__(256) kD(const float* __restrict__ Wout){
  __shared__ float As[32][33];
  __shared__ float Bs[32][32];
  int t = threadIdx.x;
  int n0 = blockIdx.x*32, m0 = blockIdx.y*32, kz = blockIdx.z;
  int ty = t>>4, tx = t&15;
  int lm = t>>3, lk = (t&7)*4;
  float acc[2][2] = {{0.f,0.f},{0.f,0.f}};
  for (int kc=kz*256; kc<kz*256+256; kc+=32){
    float4 av = *(const float4*)&g_ys[(m0+lm)*DIn + kc + lk];
    As[lk  ][lm]=av.x; As[lk+1][lm]=av.y; As[lk+2][lm]=av.z; As[lk+3][lm]=av.w;
    *(float4*)&Bs[lm][lk] = *(const float4*)&Wout[(kc+lm)*DMn + n0 + lk];
    __syncthreads();
    #pragma unroll
    for (int k=0;k<32;k++){
      float a0=As[k][ty*2], a1=As[k][ty*2+1];
      float b0=Bs[k][tx*2], b1=Bs[k][tx*2+1];
      acc[0][0]+=a0*b0; acc[0][1]+=a0*b1;
      acc[1][0]+=a1*b0; acc[1][1]+=a1*b1;
    }
    __syncthreads();
  }
  float* P = g_part[kz];
  int m = m0+ty*2, n = n0+tx*2;
  P[m*DMn+n]=acc[0][0]; P[m*DMn+n+1]=acc[0][1];
  P[(m+1)*DMn+n]=acc[1][0]; P[(m+1)*DMn+n+1]=acc[1][1];
}

// ---------------- kAddLN: x += sum(partials); g_xn = LN(x)*lnw (+ctx) ----------------
__global__ void __launch_bounds__(256) kAddLN(const float* __restrict__ lnw, int useCtx){
  __shared__ float rs_[8], rq_[8];
  __shared__ float smu, srs;
  int b = blockIdx.x, t = threadIdx.x;
  int c = 2*t;
  float2 x = ((const float2*)(g_x + b*DMn))[t];
  #pragma unroll
  for (int p=0;p<4;p++){
    float2 v = ((const float2*)(g_part[p] + b*DMn))[t];
    x.x += v.x; x.y += v.y;
  }
  ((float2*)(g_x + b*DMn))[t] = x;
  float s = x.x+x.y, q = x.x*x.x+x.y*x.y;
  for (int o=16;o;o>>=1){ s+=__shfl_xor_sync(0xffffffffu,s,o); q+=__shfl_xor_sync(0xffffffffu,q,o); }
  if ((t&31)==0){ rs_[t>>5]=s; rq_[t>>5]=q; }
  __syncthreads();
  if (t==0){
    float S=0,Q=0;
    #pragma unroll
    for (int w=0;w<8;w++){ S+=rs_[w]; Q+=rq_[w]; }
    float m=S*(1.f/DMn); smu=m; srs=rsqrtf(Q*(1.f/DMn)-m*m+1e-5f);
  }
  __syncthreads();
  float m=smu, r=srs;
  float2 xn;
  xn.x = (x.x-m)*r*lnw[c];
  xn.y = (x.y-m)*r*lnw[c+1];
  if (useCtx){
    float2 cv = ((const float2*)(g_ctx + b*DMn))[t];
    xn.x += cv.x; xn.y += cv.y;
  }
  ((float2*)(g_xn + b*DMn))[t] = xn;
}

// ---------------- kHead: head GEMM from g_xn -> raw/act/logprob ----------------
__global__ void __launch_bounds__(128) kHead(const float* __restrict__ Wh,
                      const float* __restrict__ lstd, const float* __restrict__ eps,
                      float* __restrict__ out, int i){
  __shared__ float spart[128];
  int b = blockIdx.x, t = threadIdx.x;
  const float* xn = g_xn + b*DMn;
  int j = t&15, seg = t>>4;
  float p = 0.f;
  for (int k=seg*64; k<seg*64+64; k++) p += xn[k]*Wh[k*ADn + j];
  spart[t] = p; __syncthreads();
  if (t < 16){
    float m = 0.f;
    #pragma unroll
    for (int sg=0;sg<8;sg++) m += spart[sg*16 + t];
    float std = softplusf_(lstd[t]);
    float e = eps[(b*NAn+i)*ADn + t];
    float raw = m + std*e;
    float act = tanhf(raw);
    int oidx = (b*NAn+i)*ADn + t;
    out[oidx] = act;
    out[17408 + oidx] = raw;
    g_aprev[b*ADn+t] = act;
    float term = -0.5f*e*e - logf(std)
               - 2.f*(0.69314718055994531f - raw - softplusf_(-2.f*raw));
    for (int o=8;o;o>>=1) term += __shfl_xor_sync(0xffffu, term, o);
    if (t==0) out[16384 + b*NAn + i] = term - 0.5f*ADn*1.8378770664093453f;
  }
}

extern "C" void kernel_launch(void* const* d_in, const int* in_sizes, int n_in,
                              void* d_out, int out_size){
  (void)in_sizes; (void)n_in; (void)out_size;
  const float* obs_rep =(const float*)d_in[0];
  const float* obs     =(const float*)d_in[1];
  const float* eps     =(const float*)d_in[2];
  const float* W_embed =(const float*)d_in[3];
  const float* b_embed =(const float*)d_in[4];
  const float* W_obs   =(const float*)d_in[5];
  const float* ln1     =(const float*)d_in[6];
  const float* ln2     =(const float*)d_in[7];
  const float* ln_out  =(const float*)d_in[8];
  const float* W_head  =(const float*)d_in[9];
  const float* log_std =(const float*)d_in[10];
  const float* ip [2]={(const float*)d_in[11],(const float*)d_in[20]};
  const float* cwp[2]={(const float*)d_in[12],(const float*)d_in[21]};
  const float* cbp[2]={(const float*)d_in[13],(const float*)d_in[22]};
  const float* xpj[2]={(const float*)d_in[14],(const float*)d_in[23]};
  const float* dtp[2]={(const float*)d_in[15],(const float*)d_in[24]};
  const float* dtb[2]={(const float*)d_in[16],(const float*)d_in[25]};
  const float* alp[2]={(const float*)d_in[17],(const float*)d_in[26]};
  const float* Dpp[2]={(const float*)d_in[18],(const float*)d_in[27]};
  const float* opp[2]={(const float*)d_in[19],(const float*)d_in[28]};
  float* out=(float*)d_out;

  kPrep<<<(8*DIn*DSn+255)/256,256>>>(alp[0], alp[1]);
  for (int i=0;i<NAn;i++){
    kEmbed<<<Bn,256>>>(obs_rep, obs, W_embed, b_embed, W_obs, ln1 /*block 0*/, i);
    for (int nb=0;nb<NBn;nb++){
      for (int v=0;v<2;v++){
        int inst = nb*2+v;
        kA<<<dim3(64,4),256>>>(ip[v] + (size_t)nb*DMn*2*DIn,
                               cwp[v] + nb*DCn*DIn,
                               cbp[v] + nb*DIn,
                               inst, i);
        kB1<<<dim3(4,8),256>>>(xpj[v] + (size_t)nb*DIn*96);
        kB2<<<dim3(32,4),1024>>>(dtp[v] + nb*DRn*DIn,
                                 dtb[v] + nb*DIn,
                                 Dpp[v] + nb*DIn,
                                 inst, i);
        kD<<<dim3(16,4,4),256>>>(opp[v] + (size_t)nb*DIn*DMn);
        const float* nlw; int nuc;
        if (v==0){ nlw = ln2 + nb*DMn; nuc = 1; }
        else if (nb < NBn-1){ nlw = ln1 + (nb+1)*DMn; nuc = 0; }
        else { nlw = ln_out; nuc = 0; }
        kAddLN<<<Bn,256>>>(nlw, nuc);
      }
    }
    kHead<<<Bn,128>>>(W_head, log_std, eps, out, i);
  }
}